// round 5
// baseline (speedup 1.0000x reference)
#include <cuda_runtime.h>
#include <math.h>
#include <stdint.h>

#define NB 4
#define NT 2048
#define NH 16
#define ND 64
#define NE 1024
#define NC 64
#define NCHK 32
#define NBH (NB*NH)

// ---------------- scratch (device globals; no runtime allocation) ----------------
__device__ float g_q  [(size_t)NB*NH*NT*ND];
__device__ float g_k  [(size_t)NB*NH*NT*ND];
__device__ float g_v  [(size_t)NB*NH*NT*ND];
__device__ float g_ret[(size_t)NB*NH*NT*ND];
__device__ float g_U  [(size_t)NBH*NCHK*ND*ND];
__device__ float g_S  [(size_t)NBH*NCHK*ND*ND];
__device__ float g_kvc[(size_t)NBH*NCHK*ND*ND];
__device__ float g_W  [(size_t)NBH*NCHK*ND];
__device__ float g_Xn [(size_t)NBH*NCHK*ND];
__device__ float g_stat[(size_t)NBH*NCHK*2];
__device__ float g_norm[NB*2];

__device__ __forceinline__ unsigned f2tf(float x){
    unsigned r;
    asm("cvt.rna.tf32.f32 %0, %1;" : "=r"(r) : "f"(x));
    return r;
}
__device__ __forceinline__ float tfr(float x){
    return __uint_as_float(f2tf(x));
}
__device__ __forceinline__ void mma8(float c[4], const unsigned a[4], unsigned b0, unsigned b1){
    asm volatile(
      "mma.sync.aligned.m16n8k8.row.col.f32.tf32.tf32.f32 "
      "{%0,%1,%2,%3},{%4,%5,%6,%7},{%8,%9},{%0,%1,%2,%3};"
      : "+f"(c[0]),"+f"(c[1]),"+f"(c[2]),"+f"(c[3])
      : "r"(a[0]),"r"(a[1]),"r"(a[2]),"r"(a[3]), "r"(b0),"r"(b1));
}

#define CP16(dst_u32, src) \
    asm volatile("cp.async.ca.shared.global [%0], [%1], 16;" :: "r"(dst_u32), "l"(src))

// ================= K1: fused QKV projection (TF32 mma, 256x128 tiles, 3-stage) ===
#define PROJ_SMEM (3*(5120+2176)*4)
__global__ void __launch_bounds__(512) k_proj3(const float* __restrict__ X,
                                               const float* __restrict__ Wq,
                                               const float* __restrict__ Wk,
                                               const float* __restrict__ Wv)
{
    const int sel = blockIdx.z;
    const float* W = (sel==0)?Wq:(sel==1)?Wk:Wv;
    float* dst = (sel==0)?g_q:(sel==1)?g_k:g_v;

    extern __shared__ float dsm[];
    float* As = dsm;            // 3 stages of 256*20
    float* Bs = dsm + 3*5120;   // 3 stages of 16*136

    const int tid = threadIdx.x;
    const int rowBase = blockIdx.y*256, colBase = blockIdx.x*128;
    const int warp = tid>>5, lane = tid&31;
    const int wm = warp&7, wn = warp>>3;
    const int g = lane>>2, t4 = lane&3;

    const int ar0 = tid>>2, ac0 = (tid&3)*4;
    const int br0 = tid>>5, bc0 = (tid&31)*4;

    const unsigned sA = (unsigned)__cvta_generic_to_shared(As);
    const unsigned sB = (unsigned)__cvta_generic_to_shared(Bs);
    const unsigned stA = 5120u*4u, stB = 2176u*4u;

    float acc[2][8][4];
#pragma unroll
    for (int a=0;a<2;a++)
#pragma unroll
      for (int b=0;b<8;b++)
#pragma unroll
        for (int c=0;c<4;c++) acc[a][b][c]=0.f;

    auto issue = [&](int it, int st){
        int kb = it*16;
        const float* xs = X + (size_t)rowBase*NE + kb;
        CP16(sA + st*stA + (unsigned)((ar0     )*20 + ac0)*4u, xs + (size_t)(ar0     )*NE + ac0);
        CP16(sA + st*stA + (unsigned)((ar0+128 )*20 + ac0)*4u, xs + (size_t)(ar0+128 )*NE + ac0);
        const float* ws = W + (size_t)kb*NE + colBase;
        CP16(sB + st*stB + (unsigned)(br0*136 + bc0)*4u, ws + (size_t)br0*NE + bc0);
        asm volatile("cp.async.commit_group;" ::: "memory");
    };

    const int NIT = NE/16;
    issue(0,0); issue(1,1);
    for (int it=0; it<NIT; it++){
        const int st = it%3;
        if (it+2<NIT){
            issue(it+2, (it+2)%3);
            asm volatile("cp.async.wait_group 2;" ::: "memory");
        } else if (it+1<NIT){
            asm volatile("cp.async.wait_group 1;" ::: "memory");
        } else {
            asm volatile("cp.async.wait_group 0;" ::: "memory");
        }
        __syncthreads();
        const float* Ap = As + st*5120;
        const float* Bp = Bs + st*2176;
#pragma unroll
        for (int k0=0;k0<16;k0+=8){
            unsigned af[2][4];
#pragma unroll
            for (int mt=0;mt<2;mt++){
                int r0 = wm*32 + mt*16;
                af[mt][0] = f2tf(Ap[(r0+g  )*20 + k0 + t4    ]);
                af[mt][1] = f2tf(Ap[(r0+g+8)*20 + k0 + t4    ]);
                af[mt][2] = f2tf(Ap[(r0+g  )*20 + k0 + t4 + 4]);
                af[mt][3] = f2tf(Ap[(r0+g+8)*20 + k0 + t4 + 4]);
            }
#pragma unroll
            for (int nt=0;nt<8;nt++){
                int c0 = wn*64 + nt*8;
                unsigned b0 = f2tf(Bp[(k0+t4  )*136 + c0 + g]);
                unsigned b1 = f2tf(Bp[(k0+t4+4)*136 + c0 + g]);
#pragma unroll
                for (int mt=0;mt<2;mt++){
                    mma8(acc[mt][nt], af[mt], b0, b1);
                }
            }
        }
        __syncthreads();
    }
#pragma unroll
    for (int mt=0;mt<2;mt++)
#pragma unroll
    for (int nt=0;nt<8;nt++){
        int row = rowBase + wm*32 + mt*16 + g;
        int col = colBase + wn*64 + nt*8 + t4*2;
        int b_ = row>>11, t_ = row&2047, h_ = col>>6, d_ = col&63;
        float* p0 = dst + (((size_t)(b_*NH+h_))*NT + t_)*ND + d_;
        *(float2*)p0 = make_float2(acc[mt][nt][0], acc[mt][nt][1]);
        int row2 = row+8;
        int b2_ = row2>>11, t2_ = row2&2047;
        float* p1 = dst + (((size_t)(b2_*NH+h_))*NT + t2_)*ND + d_;
        *(float2*)p1 = make_float2(acc[mt][nt][2], acc[mt][nt][3]);
    }
}

// ================= K2: per-chunk U_j, KV_j (tensor core, frag reuse), W_j =========
#define P1_SMEM ((4352 + 2*4608)*4)
__global__ void __launch_bounds__(256) k_pass1(const float* __restrict__ pkv)
{
    extern __shared__ float sm1[];
    float* bKT = sm1;          // 64x68 : K^T [d][i], tf32
    float* bV  = sm1 + 4352;   // 64x72 : V  [i][e], tf32 (later Q raw)
    float* bVw = sm1 + 4352 + 4608; // 64x72 : gamma^{63-i} V, tf32
    __shared__ float gp[65];
    __shared__ float red[4*64];
    __shared__ float qw[64];
    int tid=threadIdx.x, bid=blockIdx.x;
    int j=bid&31, bh=bid>>5, h=bh&15;
    size_t base = ((size_t)bh*NT + (size_t)j*NC)*ND;
    if (tid<=64){
        double gd = 1.0 - exp2(-5.0-(double)h);
        gp[tid]=(float)pow(gd,(double)tid);
    }
    __syncthreads();
#pragma unroll
    for (int l=0;l<4;l++){
        int idx = tid + l*256;
        int i=idx>>4, d4=(idx&15)*4;
        float4 k4 = *(const float4*)(g_k + base + (size_t)idx*4);
        bKT[(d4  )*68+i]=tfr(k4.x);
        bKT[(d4+1)*68+i]=tfr(k4.y);
        bKT[(d4+2)*68+i]=tfr(k4.z);
        bKT[(d4+3)*68+i]=tfr(k4.w);
        float4 v4 = *(const float4*)(g_v + base + (size_t)idx*4);
        bV[i*72+d4  ]=tfr(v4.x);
        bV[i*72+d4+1]=tfr(v4.y);
        bV[i*72+d4+2]=tfr(v4.z);
        bV[i*72+d4+3]=tfr(v4.w);
        float w = gp[63-i];
        bVw[i*72+d4  ]=tfr(v4.x*w);
        bVw[i*72+d4+1]=tfr(v4.y*w);
        bVw[i*72+d4+2]=tfr(v4.z*w);
        bVw[i*72+d4+3]=tfr(v4.w*w);
    }
    __syncthreads();
    const int warp=tid>>5, lane=tid&31;
    const int wm=warp&3, wn=warp>>2, g=lane>>2, t4=lane&3;
    const int m0=wm*16;
    const int r0=m0+g, r1=r0+8;

    // K^T fragments, loaded once
    unsigned ka[8][4];
#pragma unroll
    for (int k8=0;k8<8;k8++){
        int k=k8*8;
        ka[k8][0]=__float_as_uint(bKT[(m0+g  )*68 + k+t4  ]);
        ka[k8][1]=__float_as_uint(bKT[(m0+g+8)*68 + k+t4  ]);
        ka[k8][2]=__float_as_uint(bKT[(m0+g  )*68 + k+t4+4]);
        ka[k8][3]=__float_as_uint(bKT[(m0+g+8)*68 + k+t4+4]);
    }

    float accKV[4][4]={}, accU[4][4]={};
#pragma unroll
    for (int k8=0;k8<8;k8++){
#pragma unroll
        for (int nt=0;nt<4;nt++){
            int cb=wn*32+nt*8;
            unsigned b0=__float_as_uint(bV [(k8*8+t4  )*72 + cb+g]);
            unsigned b1=__float_as_uint(bV [(k8*8+t4+4)*72 + cb+g]);
            mma8(accKV[nt], ka[k8], b0, b1);
            unsigned c0=__float_as_uint(bVw[(k8*8+t4  )*72 + cb+g]);
            unsigned c1=__float_as_uint(bVw[(k8*8+t4+4)*72 + cb+g]);
            mma8(accU[nt], ka[k8], c0, c1);
        }
    }
    {
        float* Kp = g_kvc + (size_t)bid*4096;
        float* Up = g_U  + (size_t)bid*4096;
#pragma unroll
        for (int nt=0;nt<4;nt++){
            int c0=wn*32+nt*8+t4*2;
            *(float2*)(Kp + r0*64 + c0) = make_float2(accKV[nt][0],accKV[nt][1]);
            *(float2*)(Kp + r1*64 + c0) = make_float2(accKV[nt][2],accKV[nt][3]);
            *(float2*)(Up + r0*64 + c0) = make_float2(accU[nt][0],accU[nt][1]);
            *(float2*)(Up + r1*64 + c0) = make_float2(accU[nt][2],accU[nt][3]);
        }
    }
    __syncthreads();
    // Q raw into bV
#pragma unroll
    for (int l=0;l<4;l++){
        int idx=tid+l*256;
        *(float4*)(bV + (idx>>4)*72 + (idx&15)*4) =
            *(const float4*)(g_q + base + (size_t)idx*4);
    }
    __syncthreads();
    // qw[d] = sum_i gamma^i q[i,d]
    int rr = tid>>6, d = tid&63;
    float s = 0.f;
#pragma unroll
    for (int i=rr*16;i<rr*16+16;i++) s += gp[i]*bV[i*72 + d];
    red[rr*64 + d] = s;
    __syncthreads();
    if (tid<64) qw[tid] = red[tid] + red[64+tid] + red[128+tid] + red[192+tid];
    __syncthreads();
    // W_j[e] = sum_d qw[d] * A[d,e]
    const float* A = pkv + (size_t)h*4096;
    float s2 = 0.f;
#pragma unroll
    for (int dd=rr*16; dd<rr*16+16; dd++) s2 += qw[dd]*A[dd*64 + d];
    red[rr*64 + d] = s2;
    __syncthreads();
    if (tid<64) g_W[(size_t)bid*64 + tid] = red[tid] + red[64+tid] + red[128+tid] + red[192+tid];
}

// ================= K3: chunk scans (forward state, backward suffix carry) =========
__global__ void __launch_bounds__(256) k_scan()
{
    int bh = blockIdx.x, part = blockIdx.y, tid = threadIdx.x;
    int h = bh&15;
    double gd = 1.0 - exp2(-5.0-(double)h);
    float g64 = (float)pow(gd,64.0);
    float S[4] = {0.f,0.f,0.f,0.f};
    int off = part*1024;
    for (int j=0;j<NCHK;j++){
        size_t o = ((size_t)bh*NCHK+j)*4096 + off;
#pragma unroll
        for (int r=0;r<4;r++){
            int idx = tid + r*256;
            g_S[o+idx] = S[r];
            S[r] = g64*S[r] + g_U[o+idx];
        }
    }
    if (part==0 && tid<64){
        float X=0.f;
        for (int j=NCHK-1;j>=0;--j){
            size_t o2 = ((size_t)bh*NCHK+j)*64;
            g_Xn[o2+tid] = X;
            X = g64*X + g_W[o2+tid];
        }
    }
}

// ================= K4: per-chunk finalize (tensor core, frag reuse) =================
#define P3_SMEM ((4352 + 4*4608)*4)
__global__ void __launch_bounds__(256) k_pass3(const float* __restrict__ pkv)
{
    extern __shared__ float sm3[];
    float* bQ = sm3;                  // 64x68 : Q [i][d] tf32 -> P tf32
    float* bK = sm3 + 4352;           // 64x72 : K^T [d][s] tf32 -> scan buffer
    float* bS = sm3 + 4352 + 4608;    // 64x72 : S [d][e] raw fp32
    float* bA = sm3 + 4352 + 2*4608;  // 64x72 : past_kv [d][e] raw
    float* bV = sm3 + 4352 + 3*4608;  // 64x72 : V [s][e] raw
    __shared__ float gp[65];
    __shared__ float Xs[64];
    __shared__ float carry[4*64];
    __shared__ float redS[8], redQ[8];
    int tid=threadIdx.x, bid=blockIdx.x;
    int j=bid&31, bh=bid>>5, h=bh&15;
    size_t base=((size_t)bh*NT+(size_t)j*NC)*ND;

    // prefetch S, A, V raw via cp.async
    {
        const unsigned sb = (unsigned)__cvta_generic_to_shared(sm3);
        const float* Ssrc = g_S + ((size_t)bh*NCHK+j)*4096;
        const float* Asrc = pkv + (size_t)h*4096;
        const float* Vsrc = g_v + base;
#pragma unroll
        for (int l=0;l<4;l++){
            int idx=tid+l*256;
            unsigned o = (unsigned)((idx>>4)*72 + (idx&15)*4)*4u;
            CP16(sb + (4352u+  4608u)*4u + o, Ssrc + (size_t)idx*4);
            CP16(sb + (4352u+2*4608u)*4u + o, Asrc + (size_t)idx*4);
            CP16(sb + (4352u+3*4608u)*4u + o, Vsrc + (size_t)idx*4);
        }
        asm volatile("cp.async.commit_group;" ::: "memory");
    }
    if (tid<=64){
        double gd = 1.0 - exp2(-5.0-(double)h);
        gp[tid]=(float)pow(gd,(double)tid);
    }
    if (tid<64) Xs[tid] = g_Xn[((size_t)bh*NCHK+j)*64 + tid];
    // Q -> bQ (tf32), K^T -> bK (tf32)
#pragma unroll
    for (int l=0;l<4;l++){
        int idx=tid+l*256;
        int i=idx>>4, d4=(idx&15)*4;
        float4 q4 = *(const float4*)(g_q + base + (size_t)idx*4);
        bQ[i*68+d4  ]=tfr(q4.x);
        bQ[i*68+d4+1]=tfr(q4.y);
        bQ[i*68+d4+2]=tfr(q4.z);
        bQ[i*68+d4+3]=tfr(q4.w);
        float4 k4 = *(const float4*)(g_k + base + (size_t)idx*4);
        bK[(d4  )*72+i]=tfr(k4.x);
        bK[(d4+1)*72+i]=tfr(k4.y);
        bK[(d4+2)*72+i]=tfr(k4.z);
        bK[(d4+3)*72+i]=tfr(k4.w);
    }
    __syncthreads();
    const int warp=tid>>5, lane=tid&31;
    const int wm=warp&3, wn=warp>>2, g=lane>>2, t4=lane&3;
    const int m0=wm*16;
    const int r0=m0+g, r1=r0+8;

    // Q fragments, loaded once, reused for 3 mmas
    unsigned qa[8][4];
#pragma unroll
    for (int k8=0;k8<8;k8++){
        int k=k8*8;
        qa[k8][0]=__float_as_uint(bQ[(m0+g  )*68 + k+t4  ]);
        qa[k8][1]=__float_as_uint(bQ[(m0+g+8)*68 + k+t4  ]);
        qa[k8][2]=__float_as_uint(bQ[(m0+g  )*68 + k+t4+4]);
        qa[k8][3]=__float_as_uint(bQ[(m0+g+8)*68 + k+t4+4]);
    }
    // P = Q K^T  (bK already tf32)
    float accP[4][4]={};
#pragma unroll
    for (int k8=0;k8<8;k8++){
#pragma unroll
        for (int nt=0;nt<4;nt++){
            int cb=wn*32+nt*8;
            unsigned b0=__float_as_uint(bK[(k8*8+t4  )*72 + cb+g]);
            unsigned b1=__float_as_uint(bK[(k8*8+t4+4)*72 + cb+g]);
            mma8(accP[nt], qa[k8], b0, b1);
        }
    }
    asm volatile("cp.async.wait_group 0;" ::: "memory");
    __syncthreads();
    // QS = Q S, PP = Q A (raw buffers, cvt at fragment load)
    float accQ[4][4]={}, accPP[4][4]={};
#pragma unroll
    for (int k8=0;k8<8;k8++){
#pragma unroll
        for (int nt=0;nt<4;nt++){
            int cb=wn*32+nt*8;
            unsigned b0=f2tf(bS[(k8*8+t4  )*72 + cb+g]);
            unsigned b1=f2tf(bS[(k8*8+t4+4)*72 + cb+g]);
            mma8(accQ[nt], qa[k8], b0, b1);
            unsigned c0=f2tf(bA[(k8*8+t4  )*72 + cb+g]);
            unsigned c1=f2tf(bA[(k8*8+t4+4)*72 + cb+g]);
            mma8(accPP[nt], qa[k8], c0, c1);
        }
    }
    // decay P -> bQ (tf32); scale accQ by gamma^{row+1}; PP -> bK (fp32)
#pragma unroll
    for (int nt=0;nt<4;nt++){
        int c0=wn*32+nt*8+t4*2;
        int d00=r0-c0, d01=d00-1, d10=r1-c0, d11=d10-1;
        float p00 = (d00>=0)? accP[nt][0]*gp[d00] : 0.f;
        float p01 = (d01>=0)? accP[nt][1]*gp[d01] : 0.f;
        float p10 = (d10>=0)? accP[nt][2]*gp[d10] : 0.f;
        float p11 = (d11>=0)? accP[nt][3]*gp[d11] : 0.f;
        bQ[r0*68+c0  ]=tfr(p00);
        bQ[r0*68+c0+1]=tfr(p01);
        bQ[r1*68+c0  ]=tfr(p10);
        bQ[r1*68+c0+1]=tfr(p11);
        *(float2*)(bK + r0*72 + c0) = make_float2(accPP[nt][0],accPP[nt][1]);
        *(float2*)(bK + r1*72 + c0) = make_float2(accPP[nt][2],accPP[nt][3]);
        float gq0=gp[r0+1], gq1=gp[r1+1];
        accQ[nt][0]*=gq0; accQ[nt][1]*=gq0;
        accQ[nt][2]*=gq1; accQ[nt][3]*=gq1;
    }
    __syncthreads();
    // R = gamma^{i+1} QS + P V   (P fragments from bQ, V raw in bV)
#pragma unroll
    for (int k8=0;k8<8;k8++){
        int k=k8*8;
        unsigned pa[4];
        pa[0]=__float_as_uint(bQ[(m0+g  )*68 + k+t4  ]);
        pa[1]=__float_as_uint(bQ[(m0+g+8)*68 + k+t4  ]);
        pa[2]=__float_as_uint(bQ[(m0+g  )*68 + k+t4+4]);
        pa[3]=__float_as_uint(bQ[(m0+g+8)*68 + k+t4+4]);
#pragma unroll
        for (int nt=0;nt<4;nt++){
            int cb=wn*32+nt*8;
            unsigned b0=f2tf(bV[(k+t4  )*72 + cb+g]);
            unsigned b1=f2tf(bV[(k+t4+4)*72 + cb+g]);
            mma8(accQ[nt], pa, b0, b1);
        }
    }
    // suffix scan of PP (bK, stride 72): quarters of 16 rows, serial in regs
    {
        int e = tid&63, q = tid>>6;
        float g1 = gp[1];
        float loc[16];
        float c = 0.f;
#pragma unroll
        for (int i=15;i>=0;--i){
            c = bK[(q*16+i)*72 + e] + g1*c;
            loc[i] = c;
        }
        carry[q*64+e] = loc[0];
        __syncthreads();
        float F = 0.f;
        if (q<3) F  = carry[(q+1)*64+e];
        if (q<2) F += gp[16]*carry[(q+2)*64+e];
        if (q<1) F += gp[32]*carry[(q+3)*64+e];
#pragma unroll
        for (int i=0;i<16;i++){
            bK[(q*16+i)*72 + e] = loc[i] + gp[16-i]*F;
        }
    }
    __syncthreads();
    // final add + stats + store
    float s1=0.f, s2=0.f;
    float gx0=gp[64-r0], gx1=gp[64-r1];
#pragma unroll
    for (int nt=0;nt<4;nt++){
        int c0=wn*32+nt*8+t4*2;
        float v00 = accQ[nt][0] + bK[r0*72+c0  ] + gx0*Xs[c0  ];
        float v01 = accQ[nt][1] + bK[r0*72+c0+1] + gx0*Xs[c0+1];
        float v10 = accQ[nt][2] + bK[r1*72+c0  ] + gx1*Xs[c0  ];
        float v11 = accQ[nt][3] + bK[r1*72+c0+1] + gx1*Xs[c0+1];
        s1 += v00+v01+v10+v11;
        s2 += v00*v00+v01*v01+v10*v10+v11*v11;
        *(float2*)(g_ret + base + (size_t)r0*64 + c0) = make_float2(v00,v01);
        *(float2*)(g_ret + base + (size_t)r1*64 + c0) = make_float2(v10,v11);
    }
#pragma unroll
    for (int o=16;o>0;o>>=1){
        s1 += __shfl_down_sync(0xffffffffu, s1, o);
        s2 += __shfl_down_sync(0xffffffffu, s2, o);
    }
    if (lane==0){ redS[warp]=s1; redQ[warp]=s2; }
    __syncthreads();
    if (tid==0){
        float a=0.f,bq=0.f;
#pragma unroll
        for (int w=0;w<8;w++){ a+=redS[w]; bq+=redQ[w]; }
        g_stat[(size_t)bid*2  ]=a;
        g_stat[(size_t)bid*2+1]=bq;
    }
}

// ================= K5: per-batch GroupNorm stats =================
__global__ void __launch_bounds__(512) k_stats()
{
    __shared__ float r1[512], r2[512];
    int b=blockIdx.x, tid=threadIdx.x;
    r1[tid]=g_stat[(size_t)(b*512+tid)*2];
    r2[tid]=g_stat[(size_t)(b*512+tid)*2+1];
    __syncthreads();
    for (int o=256;o>0;o>>=1){
        if (tid<o){ r1[tid]+=r1[tid+o]; r2[tid]+=r2[tid+o]; }
        __syncthreads();
    }
    if (tid==0){
        const float N = (float)((size_t)NH*NT*ND);
        float mu = r1[0]/N;
        float var = r2[0]/N - mu*mu;
        g_norm[b*2]=mu;
        g_norm[b*2+1]=rsqrtf(var+1e-5f);
    }
}

// ================= K6: normalize + layout to [B,T,NE] =================
__global__ void __launch_bounds__(256) k_out(const float* __restrict__ gnw,
                                             const float* __restrict__ gnb,
                                             float* __restrict__ out)
{
    int bid=blockIdx.x;
    int b=bid>>11, t=bid&2047;
    int tid=threadIdx.x;
    int h=tid>>4, d4=(tid&15)*4;
    float mu=g_norm[b*2], rs=g_norm[b*2+1];
    float w = gnw[h]*rs;
    float bb = gnb[h] - mu*w;
    float4 xv = *(const float4*)(g_ret + (((size_t)(b*NH+h))*NT + t)*ND + d4);
    float4 yv = make_float4(xv.x*w+bb, xv.y*w+bb, xv.z*w+bb, xv.w*w+bb);
    *(float4*)(out + (size_t)bid*NE + h*ND + d4) = yv;
}

// ================= K7: kv reduce + decay =================
__global__ void __launch_bounds__(256) k_kvout(const float* __restrict__ pkv,
                                               float* __restrict__ out_kv)
{
    int h=blockIdx.x;
    int idx=blockIdx.y*256+threadIdx.x;
    float s=0.f;
    for (int b=0;b<NB;b++){
        size_t bh=((size_t)(b*NH+h))*NCHK;
        for (int j2=0;j2<NCHK;j2++) s += g_kvc[(bh+j2)*4096 + idx];
    }
    double gd = 1.0 - exp2(-5.0-(double)h);
    out_kv[(size_t)h*4096 + idx] = (float)gd*pkv[(size_t)h*4096 + idx] + 0.25f*s;
}

extern "C" void kernel_launch(void* const* d_in, const int* in_sizes, int n_in,
                              void* d_out, int out_size)
{
    const float* x   = (const float*)d_in[0];
    const float* pkv = (const float*)d_in[1];
    const float* Wq  = (const float*)d_in[2];
    const float* Wk  = (const float*)d_in[3];
    const float* Wv  = (const float*)d_in[4];
    const float* gnw = (const float*)d_in[5];
    const float* gnb = (const float*)d_in[6];
    float* out = (float*)d_out;

    cudaFuncSetAttribute(k_proj3, cudaFuncAttributeMaxDynamicSharedMemorySize, PROJ_SMEM);
    cudaFuncSetAttribute(k_pass1, cudaFuncAttributeMaxDynamicSharedMemorySize, P1_SMEM);
    cudaFuncSetAttribute(k_pass3, cudaFuncAttributeMaxDynamicSharedMemorySize, P3_SMEM);

    dim3 gproj(8, 32, 3);
    k_proj3<<<gproj, 512, PROJ_SMEM>>>(x, Wq, Wk, Wv);
    k_pass1<<<NBH*NCHK, 256, P1_SMEM>>>(pkv);
    dim3 gscan(NBH, 4);
    k_scan<<<gscan, 256>>>();
    k_pass3<<<NBH*NCHK, 256, P3_SMEM>>>(pkv);
    k_stats<<<NB, 512>>>();
    k_out<<<NB*NT, 256>>>(gnw, gnb, out);
    dim3 gkv(NH, 16);
    k_kvout<<<gkv, 256>>>(pkv, out + (size_t)NB*NT*NE);
}

// round 6
// speedup vs baseline: 1.1242x; 1.1242x over previous
#include <cuda_runtime.h>
#include <math.h>
#include <stdint.h>

#define NB 4
#define NT 2048
#define NH 16
#define ND 64
#define NE 1024
#define NC 64
#define NCHK 32
#define NBH (NB*NH)

// ---------------- scratch (device globals; no runtime allocation) ----------------
__device__ float g_q  [(size_t)NB*NH*NT*ND];
__device__ float g_k  [(size_t)NB*NH*NT*ND];
__device__ float g_v  [(size_t)NB*NH*NT*ND];
__device__ float g_ret[(size_t)NB*NH*NT*ND];
__device__ float g_U  [(size_t)NBH*NCHK*ND*ND];
__device__ float g_S  [(size_t)NBH*NCHK*ND*ND];
__device__ float g_kvc[(size_t)NBH*NCHK*ND*ND];
__device__ float g_W  [(size_t)NBH*NCHK*ND];
__device__ float g_Xn [(size_t)NBH*NCHK*ND];
__device__ float g_stat[(size_t)NBH*NCHK*2];
__device__ float g_norm[NB*2];
__device__ float g_xr [(size_t)NB*NT*NE];    // tf32-rounded X
__device__ float g_wr [(size_t)3*NE*NE];     // tf32-rounded Wq,Wk,Wv

__device__ __forceinline__ unsigned f2tf(float x){
    unsigned r;
    asm("cvt.rna.tf32.f32 %0, %1;" : "=r"(r) : "f"(x));
    return r;
}
__device__ __forceinline__ float tfr(float x){
    return __uint_as_float(f2tf(x));
}
__device__ __forceinline__ void mma8(float c[4], const unsigned a[4], unsigned b0, unsigned b1){
    asm volatile(
      "mma.sync.aligned.m16n8k8.row.col.f32.tf32.tf32.f32 "
      "{%0,%1,%2,%3},{%4,%5,%6,%7},{%8,%9},{%0,%1,%2,%3};"
      : "+f"(c[0]),"+f"(c[1]),"+f"(c[2]),"+f"(c[3])
      : "r"(a[0]),"r"(a[1]),"r"(a[2]),"r"(a[3]), "r"(b0),"r"(b1));
}

#define CP16(dst_u32, src) \
    asm volatile("cp.async.ca.shared.global [%0], [%1], 16;" :: "r"(dst_u32), "l"(src))

// ================= K0: pre-round X and W to tf32 =================
#define NX4 ((NB*NT*NE)/4)       // 2097152
#define NW4 ((NE*NE)/4)          // 262144
__global__ void __launch_bounds__(256) k_cvt(const float* __restrict__ X,
                                             const float* __restrict__ Wq,
                                             const float* __restrict__ Wk,
                                             const float* __restrict__ Wv)
{
    int i = blockIdx.x*256 + threadIdx.x;
    const float4* src;
    float4* dst;
    int off;
    if (i < NX4){
        src = (const float4*)X; dst = (float4*)g_xr; off = i;
    } else {
        int i2 = i - NX4;
        int sel = i2 / NW4; off = i2 - sel*NW4;
        src = (const float4*)((sel==0)?Wq:(sel==1)?Wk:Wv);
        dst = (float4*)(g_wr + (size_t)sel*NE*NE);
    }
    float4 v = src[off];
    v.x=tfr(v.x); v.y=tfr(v.y); v.z=tfr(v.z); v.w=tfr(v.w);
    dst[off] = v;
}

// ================= K1: fused QKV projection (TF32 mma, 128x128, 3-stage) ===
#define PROJ_SMEM (3*(2560+2176)*4)
__global__ void __launch_bounds__(256) k_proj3()
{
    const int sel = blockIdx.z;
    const float* X = g_xr;
    const float* W = g_wr + (size_t)sel*NE*NE;
    float* dst = (sel==0)?g_q:(sel==1)?g_k:g_v;

    extern __shared__ float dsm[];
    float* As = dsm;            // 3 stages of 128*20
    float* Bs = dsm + 3*2560;   // 3 stages of 16*136

    const int tid = threadIdx.x;
    const int rowBase = blockIdx.y*128, colBase = blockIdx.x*128;
    const int warp = tid>>5, lane = tid&31;
    const int wm = warp&3, wn = warp>>2;
    const int g = lane>>2, t4 = lane&3;

    const int ar0 = tid>>2, ac0 = (tid&3)*4;
    const int br0 = tid>>5, bc0 = (tid&31)*4;

    const unsigned sA = (unsigned)__cvta_generic_to_shared(As);
    const unsigned sB = (unsigned)__cvta_generic_to_shared(Bs);
    const unsigned stA = 2560u*4u, stB = 2176u*4u;

    float acc[2][8][4];
#pragma unroll
    for (int a=0;a<2;a++)
#pragma unroll
      for (int b=0;b<8;b++)
#pragma unroll
        for (int c=0;c<4;c++) acc[a][b][c]=0.f;

    auto issue = [&](int it, int st){
        int kb = it*16;
        const float* xs = X + (size_t)rowBase*NE + kb;
        CP16(sA + st*stA + (unsigned)((ar0    )*20 + ac0)*4u, xs + (size_t)(ar0    )*NE + ac0);
        CP16(sA + st*stA + (unsigned)((ar0+64 )*20 + ac0)*4u, xs + (size_t)(ar0+64 )*NE + ac0);
        const float* ws = W + (size_t)kb*NE + colBase;
        CP16(sB + st*stB + (unsigned)((br0   )*136 + bc0)*4u, ws + (size_t)(br0   )*NE + bc0);
        CP16(sB + st*stB + (unsigned)((br0+8 )*136 + bc0)*4u, ws + (size_t)(br0+8 )*NE + bc0);
        asm volatile("cp.async.commit_group;" ::: "memory");
    };

    const int NIT = NE/16;
    issue(0,0); issue(1,1);
    for (int it=0; it<NIT; it++){
        const int st = it%3;
        if (it+2<NIT){
            issue(it+2, (it+2)%3);
            asm volatile("cp.async.wait_group 2;" ::: "memory");
        } else if (it+1<NIT){
            asm volatile("cp.async.wait_group 1;" ::: "memory");
        } else {
            asm volatile("cp.async.wait_group 0;" ::: "memory");
        }
        __syncthreads();
        const float* Ap = As + st*2560;
        const float* Bp = Bs + st*2176;
#pragma unroll
        for (int k0=0;k0<16;k0+=8){
            unsigned af[2][4];
#pragma unroll
            for (int mt=0;mt<2;mt++){
                int r0 = wm*32 + mt*16;
                af[mt][0] = __float_as_uint(Ap[(r0+g  )*20 + k0 + t4    ]);
                af[mt][1] = __float_as_uint(Ap[(r0+g+8)*20 + k0 + t4    ]);
                af[mt][2] = __float_as_uint(Ap[(r0+g  )*20 + k0 + t4 + 4]);
                af[mt][3] = __float_as_uint(Ap[(r0+g+8)*20 + k0 + t4 + 4]);
            }
#pragma unroll
            for (int nt=0;nt<8;nt++){
                int c0 = wn*64 + nt*8;
                unsigned b0 = __float_as_uint(Bp[(k0+t4  )*136 + c0 + g]);
                unsigned b1 = __float_as_uint(Bp[(k0+t4+4)*136 + c0 + g]);
#pragma unroll
                for (int mt=0;mt<2;mt++){
                    mma8(acc[mt][nt], af[mt], b0, b1);
                }
            }
        }
        __syncthreads();
    }
#pragma unroll
    for (int mt=0;mt<2;mt++)
#pragma unroll
    for (int nt=0;nt<8;nt++){
        int row = rowBase + wm*32 + mt*16 + g;
        int col = colBase + wn*64 + nt*8 + t4*2;
        int b_ = row>>11, t_ = row&2047, h_ = col>>6, d_ = col&63;
        float* p0 = dst + (((size_t)(b_*NH+h_))*NT + t_)*ND + d_;
        *(float2*)p0 = make_float2(acc[mt][nt][0], acc[mt][nt][1]);
        int t2_ = (row+8)&2047;
        float* p1 = dst + (((size_t)(b_*NH+h_))*NT + t2_)*ND + d_;
        *(float2*)p1 = make_float2(acc[mt][nt][2], acc[mt][nt][3]);
    }
}

// ================= K2: per-chunk U_j, KV_j (tensor core, frag reuse), W_j =========
#define P1_SMEM ((4352 + 2*4608)*4)
__global__ void __launch_bounds__(256) k_pass1(const float* __restrict__ pkv)
{
    extern __shared__ float sm1[];
    float* bKT = sm1;          // 64x68 : K^T [d][i], tf32
    float* bV  = sm1 + 4352;   // 64x72 : V  [i][e], tf32 (later Q raw)
    float* bVw = sm1 + 4352 + 4608; // 64x72 : gamma^{63-i} V, tf32
    __shared__ float gp[65];
    __shared__ float red[4*64];
    __shared__ float qw[64];
    int tid=threadIdx.x, bid=blockIdx.x;
    int j=bid&31, bh=bid>>5, h=bh&15;
    size_t base = ((size_t)bh*NT + (size_t)j*NC)*ND;
    if (tid<=64){
        double gd = 1.0 - exp2(-5.0-(double)h);
        gp[tid]=(float)pow(gd,(double)tid);
    }
    __syncthreads();
#pragma unroll
    for (int l=0;l<4;l++){
        int idx = tid + l*256;
        int i=idx>>4, d4=(idx&15)*4;
        float4 k4 = *(const float4*)(g_k + base + (size_t)idx*4);
        bKT[(d4  )*68+i]=tfr(k4.x);
        bKT[(d4+1)*68+i]=tfr(k4.y);
        bKT[(d4+2)*68+i]=tfr(k4.z);
        bKT[(d4+3)*68+i]=tfr(k4.w);
        float4 v4 = *(const float4*)(g_v + base + (size_t)idx*4);
        bV[i*72+d4  ]=tfr(v4.x);
        bV[i*72+d4+1]=tfr(v4.y);
        bV[i*72+d4+2]=tfr(v4.z);
        bV[i*72+d4+3]=tfr(v4.w);
        float w = gp[63-i];
        bVw[i*72+d4  ]=tfr(v4.x*w);
        bVw[i*72+d4+1]=tfr(v4.y*w);
        bVw[i*72+d4+2]=tfr(v4.z*w);
        bVw[i*72+d4+3]=tfr(v4.w*w);
    }
    __syncthreads();
    const int warp=tid>>5, lane=tid&31;
    const int wm=warp&3, wn=warp>>2, g=lane>>2, t4=lane&3;
    const int m0=wm*16;
    const int r0=m0+g, r1=r0+8;

    unsigned ka[8][4];
#pragma unroll
    for (int k8=0;k8<8;k8++){
        int k=k8*8;
        ka[k8][0]=__float_as_uint(bKT[(m0+g  )*68 + k+t4  ]);
        ka[k8][1]=__float_as_uint(bKT[(m0+g+8)*68 + k+t4  ]);
        ka[k8][2]=__float_as_uint(bKT[(m0+g  )*68 + k+t4+4]);
        ka[k8][3]=__float_as_uint(bKT[(m0+g+8)*68 + k+t4+4]);
    }

    float accKV[4][4]={}, accU[4][4]={};
#pragma unroll
    for (int k8=0;k8<8;k8++){
#pragma unroll
        for (int nt=0;nt<4;nt++){
            int cb=wn*32+nt*8;
            unsigned b0=__float_as_uint(bV [(k8*8+t4  )*72 + cb+g]);
            unsigned b1=__float_as_uint(bV [(k8*8+t4+4)*72 + cb+g]);
            mma8(accKV[nt], ka[k8], b0, b1);
            unsigned c0=__float_as_uint(bVw[(k8*8+t4  )*72 + cb+g]);
            unsigned c1=__float_as_uint(bVw[(k8*8+t4+4)*72 + cb+g]);
            mma8(accU[nt], ka[k8], c0, c1);
        }
    }
    {
        float* Kp = g_kvc + (size_t)bid*4096;
        float* Up = g_U  + (size_t)bid*4096;
#pragma unroll
        for (int nt=0;nt<4;nt++){
            int c0=wn*32+nt*8+t4*2;
            *(float2*)(Kp + r0*64 + c0) = make_float2(accKV[nt][0],accKV[nt][1]);
            *(float2*)(Kp + r1*64 + c0) = make_float2(accKV[nt][2],accKV[nt][3]);
            *(float2*)(Up + r0*64 + c0) = make_float2(accU[nt][0],accU[nt][1]);
            *(float2*)(Up + r1*64 + c0) = make_float2(accU[nt][2],accU[nt][3]);
        }
    }
    __syncthreads();
#pragma unroll
    for (int l=0;l<4;l++){
        int idx=tid+l*256;
        *(float4*)(bV + (idx>>4)*72 + (idx&15)*4) =
            *(const float4*)(g_q + base + (size_t)idx*4);
    }
    __syncthreads();
    int rr = tid>>6, d = tid&63;
    float s = 0.f;
#pragma unroll
    for (int i=rr*16;i<rr*16+16;i++) s += gp[i]*bV[i*72 + d];
    red[rr*64 + d] = s;
    __syncthreads();
    if (tid<64) qw[tid] = red[tid] + red[64+tid] + red[128+tid] + red[192+tid];
    __syncthreads();
    const float* A = pkv + (size_t)h*4096;
    float s2 = 0.f;
#pragma unroll
    for (int dd=rr*16; dd<rr*16+16; dd++) s2 += qw[dd]*A[dd*64 + d];
    red[rr*64 + d] = s2;
    __syncthreads();
    if (tid<64) g_W[(size_t)bid*64 + tid] = red[tid] + red[64+tid] + red[128+tid] + red[192+tid];
}

// ================= K3: chunk scans (forward state, backward suffix carry) =========
__global__ void __launch_bounds__(256) k_scan()
{
    int bh = blockIdx.x, part = blockIdx.y, tid = threadIdx.x;
    int h = bh&15;
    double gd = 1.0 - exp2(-5.0-(double)h);
    float g64 = (float)pow(gd,64.0);
    float S[4] = {0.f,0.f,0.f,0.f};
    int off = part*1024;
    for (int j=0;j<NCHK;j++){
        size_t o = ((size_t)bh*NCHK+j)*4096 + off;
#pragma unroll
        for (int r=0;r<4;r++){
            int idx = tid + r*256;
            g_S[o+idx] = S[r];
            S[r] = g64*S[r] + g_U[o+idx];
        }
    }
    if (part==0 && tid<64){
        float X=0.f;
        for (int j=NCHK-1;j>=0;--j){
            size_t o2 = ((size_t)bh*NCHK+j)*64;
            g_Xn[o2+tid] = X;
            X = g64*X + g_W[o2+tid];
        }
    }
}

// ================= K4: per-chunk finalize (tensor core, frag reuse) =================
#define P3_SMEM ((4352 + 4*4608)*4)
__global__ void __launch_bounds__(256) k_pass3(const float* __restrict__ pkv)
{
    extern __shared__ float sm3[];
    float* bQ = sm3;                  // 64x68 : Q [i][d] tf32 -> P tf32
    float* bK = sm3 + 4352;           // 64x72 : K^T [d][s] tf32 -> scan buffer
    float* bS = sm3 + 4352 + 4608;    // 64x72 : S raw fp32
    float* bA = sm3 + 4352 + 2*4608;  // 64x72 : past_kv raw
    float* bV = sm3 + 4352 + 3*4608;  // 64x72 : V raw
    __shared__ float gp[65];
    __shared__ float Xs[64];
    __shared__ float carry[4*64];
    __shared__ float redS[8], redQ[8];
    int tid=threadIdx.x, bid=blockIdx.x;
    int j=bid&31, bh=bid>>5, h=bh&15;
    size_t base=((size_t)bh*NT+(size_t)j*NC)*ND;

    {
        const unsigned sb = (unsigned)__cvta_generic_to_shared(sm3);
        const float* Ssrc = g_S + ((size_t)bh*NCHK+j)*4096;
        const float* Asrc = pkv + (size_t)h*4096;
        const float* Vsrc = g_v + base;
#pragma unroll
        for (int l=0;l<4;l++){
            int idx=tid+l*256;
            unsigned o = (unsigned)((idx>>4)*72 + (idx&15)*4)*4u;
            CP16(sb + (4352u+  4608u)*4u + o, Ssrc + (size_t)idx*4);
            CP16(sb + (4352u+2*4608u)*4u + o, Asrc + (size_t)idx*4);
            CP16(sb + (4352u+3*4608u)*4u + o, Vsrc + (size_t)idx*4);
        }
        asm volatile("cp.async.commit_group;" ::: "memory");
    }
    if (tid<=64){
        double gd = 1.0 - exp2(-5.0-(double)h);
        gp[tid]=(float)pow(gd,(double)tid);
    }
    if (tid<64) Xs[tid] = g_Xn[((size_t)bh*NCHK+j)*64 + tid];
#pragma unroll
    for (int l=0;l<4;l++){
        int idx=tid+l*256;
        int i=idx>>4, d4=(idx&15)*4;
        float4 q4 = *(const float4*)(g_q + base + (size_t)idx*4);
        bQ[i*68+d4  ]=tfr(q4.x);
        bQ[i*68+d4+1]=tfr(q4.y);
        bQ[i*68+d4+2]=tfr(q4.z);
        bQ[i*68+d4+3]=tfr(q4.w);
        float4 k4 = *(const float4*)(g_k + base + (size_t)idx*4);
        bK[(d4  )*72+i]=tfr(k4.x);
        bK[(d4+1)*72+i]=tfr(k4.y);
        bK[(d4+2)*72+i]=tfr(k4.z);
        bK[(d4+3)*72+i]=tfr(k4.w);
    }
    __syncthreads();
    const int warp=tid>>5, lane=tid&31;
    const int wm=warp&3, wn=warp>>2, g=lane>>2, t4=lane&3;
    const int m0=wm*16;
    const int r0=m0+g, r1=r0+8;

    unsigned qa[8][4];
#pragma unroll
    for (int k8=0;k8<8;k8++){
        int k=k8*8;
        qa[k8][0]=__float_as_uint(bQ[(m0+g  )*68 + k+t4  ]);
        qa[k8][1]=__float_as_uint(bQ[(m0+g+8)*68 + k+t4  ]);
        qa[k8][2]=__float_as_uint(bQ[(m0+g  )*68 + k+t4+4]);
        qa[k8][3]=__float_as_uint(bQ[(m0+g+8)*68 + k+t4+4]);
    }
    float accP[4][4]={};
#pragma unroll
    for (int k8=0;k8<8;k8++){
#pragma unroll
        for (int nt=0;nt<4;nt++){
            int cb=wn*32+nt*8;
            unsigned b0=__float_as_uint(bK[(k8*8+t4  )*72 + cb+g]);
            unsigned b1=__float_as_uint(bK[(k8*8+t4+4)*72 + cb+g]);
            mma8(accP[nt], qa[k8], b0, b1);
        }
    }
    asm volatile("cp.async.wait_group 0;" ::: "memory");
    __syncthreads();
    float accQ[4][4]={}, accPP[4][4]={};
#pragma unroll
    for (int k8=0;k8<8;k8++){
#pragma unroll
        for (int nt=0;nt<4;nt++){
            int cb=wn*32+nt*8;
            unsigned b0=f2tf(bS[(k8*8+t4  )*72 + cb+g]);
            unsigned b1=f2tf(bS[(k8*8+t4+4)*72 + cb+g]);
            mma8(accQ[nt], qa[k8], b0, b1);
            unsigned c0=f2tf(bA[(k8*8+t4  )*72 + cb+g]);
            unsigned c1=f2tf(bA[(k8*8+t4+4)*72 + cb+g]);
            mma8(accPP[nt], qa[k8], c0, c1);
        }
    }
#pragma unroll
    for (int nt=0;nt<4;nt++){
        int c0=wn*32+nt*8+t4*2;
        int d00=r0-c0, d01=d00-1, d10=r1-c0, d11=d10-1;
        float p00 = (d00>=0)? accP[nt][0]*gp[d00] : 0.f;
        float p01 = (d01>=0)? accP[nt][1]*gp[d01] : 0.f;
        float p10 = (d10>=0)? accP[nt][2]*gp[d10] : 0.f;
        float p11 = (d11>=0)? accP[nt][3]*gp[d11] : 0.f;
        bQ[r0*68+c0  ]=tfr(p00);
        bQ[r0*68+c0+1]=tfr(p01);
        bQ[r1*68+c0  ]=tfr(p10);
        bQ[r1*68+c0+1]=tfr(p11);
        *(float2*)(bK + r0*72 + c0) = make_float2(accPP[nt][0],accPP[nt][1]);
        *(float2*)(bK + r1*72 + c0) = make_float2(accPP[nt][2],accPP[nt][3]);
        float gq0=gp[r0+1], gq1=gp[r1+1];
        accQ[nt][0]*=gq0; accQ[nt][1]*=gq0;
        accQ[nt][2]*=gq1; accQ[nt][3]*=gq1;
    }
    __syncthreads();
#pragma unroll
    for (int k8=0;k8<8;k8++){
        int k=k8*8;
        unsigned pa[4];
        pa[0]=__float_as_uint(bQ[(m0+g  )*68 + k+t4  ]);
        pa[1]=__float_as_uint(bQ[(m0+g+8)*68 + k+t4  ]);
        pa[2]=__float_as_uint(bQ[(m0+g  )*68 + k+t4+4]);
        pa[3]=__float_as_uint(bQ[(m0+g+8)*68 + k+t4+4]);
#pragma unroll
        for (int nt=0;nt<4;nt++){
            int cb=wn*32+nt*8;
            unsigned b0=f2tf(bV[(k+t4  )*72 + cb+g]);
            unsigned b1=f2tf(bV[(k+t4+4)*72 + cb+g]);
            mma8(accQ[nt], pa, b0, b1);
        }
    }
    {
        int e = tid&63, q = tid>>6;
        float g1 = gp[1];
        float loc[16];
        float c = 0.f;
#pragma unroll
        for (int i=15;i>=0;--i){
            c = bK[(q*16+i)*72 + e] + g1*c;
            loc[i] = c;
        }
        carry[q*64+e] = loc[0];
        __syncthreads();
        float F = 0.f;
        if (q<3) F  = carry[(q+1)*64+e];
        if (q<2) F += gp[16]*carry[(q+2)*64+e];
        if (q<1) F += gp[32]*carry[(q+3)*64+e];
#pragma unroll
        for (int i=0;i<16;i++){
            bK[(q*16+i)*72 + e] = loc[i] + gp[16-i]*F;
        }
    }
    __syncthreads();
    float s1=0.f, s2=0.f;
    float gx0=gp[64-r0], gx1=gp[64-r1];
#pragma unroll
    for (int nt=0;nt<4;nt++){
        int c0=wn*32+nt*8+t4*2;
        float v00 = accQ[nt][0] + bK[r0*72+c0  ] + gx0*Xs[c0  ];
        float v01 = accQ[nt][1] + bK[r0*72+c0+1] + gx0*Xs[c0+1];
        float v10 = accQ[nt][2] + bK[r1*72+c0  ] + gx1*Xs[c0  ];
        float v11 = accQ[nt][3] + bK[r1*72+c0+1] + gx1*Xs[c0+1];
        s1 += v00+v01+v10+v11;
        s2 += v00*v00+v01*v01+v10*v10+v11*v11;
        *(float2*)(g_ret + base + (size_t)r0*64 + c0) = make_float2(v00,v01);
        *(float2*)(g_ret + base + (size_t)r1*64 + c0) = make_float2(v10,v11);
    }
#pragma unroll
    for (int o=16;o>0;o>>=1){
        s1 += __shfl_down_sync(0xffffffffu, s1, o);
        s2 += __shfl_down_sync(0xffffffffu, s2, o);
    }
    if (lane==0){ redS[warp]=s1; redQ[warp]=s2; }
    __syncthreads();
    if (tid==0){
        float a=0.f,bq=0.f;
#pragma unroll
        for (int w=0;w<8;w++){ a+=redS[w]; bq+=redQ[w]; }
        g_stat[(size_t)bid*2  ]=a;
        g_stat[(size_t)bid*2+1]=bq;
    }
}

// ================= K5: per-batch GroupNorm stats =================
__global__ void __launch_bounds__(512) k_stats()
{
    __shared__ float r1[512], r2[512];
    int b=blockIdx.x, tid=threadIdx.x;
    r1[tid]=g_stat[(size_t)(b*512+tid)*2];
    r2[tid]=g_stat[(size_t)(b*512+tid)*2+1];
    __syncthreads();
    for (int o=256;o>0;o>>=1){
        if (tid<o){ r1[tid]+=r1[tid+o]; r2[tid]+=r2[tid+o]; }
        __syncthreads();
    }
    if (tid==0){
        const float N = (float)((size_t)NH*NT*ND);
        float mu = r1[0]/N;
        float var = r2[0]/N - mu*mu;
        g_norm[b*2]=mu;
        g_norm[b*2+1]=rsqrtf(var+1e-5f);
    }
}

// ================= K6: normalize + layout to [B,T,NE] =================
__global__ void __launch_bounds__(256) k_out(const float* __restrict__ gnw,
                                             const float* __restrict__ gnb,
                                             float* __restrict__ out)
{
    int bid=blockIdx.x;
    int b=bid>>11, t=bid&2047;
    int tid=threadIdx.x;
    int h=tid>>4, d4=(tid&15)*4;
    float mu=g_norm[b*2], rs=g_norm[b*2+1];
    float w = gnw[h]*rs;
    float bb = gnb[h] - mu*w;
    float4 xv = *(const float4*)(g_ret + (((size_t)(b*NH+h))*NT + t)*ND + d4);
    float4 yv = make_float4(xv.x*w+bb, xv.y*w+bb, xv.z*w+bb, xv.w*w+bb);
    *(float4*)(out + (size_t)bid*NE + h*ND + d4) = yv;
}

// ================= K7: kv reduce + decay =================
__global__ void __launch_bounds__(256) k_kvout(const float* __restrict__ pkv,
                                               float* __restrict__ out_kv)
{
    int h=blockIdx.x;
    int idx=blockIdx.y*256+threadIdx.x;
    float s=0.f;
    for (int b=0;b<NB;b++){
        size_t bh=((size_t)(b*NH+h))*NCHK;
        for (int j2=0;j2<NCHK;j2++) s += g_kvc[(bh+j2)*4096 + idx];
    }
    double gd = 1.0 - exp2(-5.0-(double)h);
    out_kv[(size_t)h*4096 + idx] = (float)gd*pkv[(size_t)h*4096 + idx] + 0.25f*s;
}

extern "C" void kernel_launch(void* const* d_in, const int* in_sizes, int n_in,
                              void* d_out, int out_size)
{
    const float* x   = (const float*)d_in[0];
    const float* pkv = (const float*)d_in[1];
    const float* Wq  = (const float*)d_in[2];
    const float* Wk  = (const float*)d_in[3];
    const float* Wv  = (const float*)d_in[4];
    const float* gnw = (const float*)d_in[5];
    const float* gnb = (const float*)d_in[6];
    float* out = (float*)d_out;

    cudaFuncSetAttribute(k_proj3, cudaFuncAttributeMaxDynamicSharedMemorySize, PROJ_SMEM);
    cudaFuncSetAttribute(k_pass1, cudaFuncAttributeMaxDynamicSharedMemorySize, P1_SMEM);
    cudaFuncSetAttribute(k_pass3, cudaFuncAttributeMaxDynamicSharedMemorySize, P3_SMEM);

    k_cvt<<<(NX4 + 3*NW4)/256, 256>>>(x, Wq, Wk, Wv);
    dim3 gproj(8, 64, 3);
    k_proj3<<<gproj, 256, PROJ_SMEM>>>();
    k_pass1<<<NBH*NCHK, 256, P1_SMEM>>>(pkv);
    dim3 gscan(NBH, 4);
    k_scan<<<gscan, 256>>>();
    k_pass3<<<NBH*NCHK, 256, P3_SMEM>>>(pkv);
    k_stats<<<NB, 512>>>();
    k_out<<<NB*NT, 256>>>(gnw, gnb, out);
    dim3 gkv(NH, 16);
    k_kvout<<<gkv, 256>>>(pkv, out + (size_t)NB*NT*NE);
}